// round 10
// baseline (speedup 1.0000x reference)
#include <cuda_runtime.h>
#include <cuda_fp16.h>
#include <math.h>
#include <stdint.h>

// ---------------- problem constants ----------------
#define Bq   8
#define Nq   1024
#define Dq   1024
#define Hq   16
#define DFFq 4096
#define FACTORq 0.125f
#define QSCALE 0.18033688f   // 0.125 * log2(e)

// ---------------- scratch (device globals) ----------------
__device__ __half g_z[(size_t)Bq * Nq * Dq];
__device__ __half g_qkv[(size_t)Bq * Nq * 3 * Dq];
__device__ float  g_s1[(size_t)Bq * Nq * Dq];
__device__ __half g_h1[(size_t)Bq * Nq * DFFq];
__device__ __half g_whqkv[(size_t)Dq * 3 * Dq];
__device__ __half g_wh1[(size_t)Dq * DFFq];
__device__ __half g_wh2[(size_t)DFFq * Dq];
__device__ __half g_pah[(size_t)Bq * Nq * Nq];   // prior * alpha*F*log2e, half

#define EPI_QKV    0
#define EPI_GELU   1
#define EPI_RES    2

// ---------------- PTX helpers (sm_90+ generic ISA only) ----------------
__device__ __forceinline__ uint32_t smem_u32(const void* p) {
    uint32_t a;
    asm("{ .reg .u64 t; cvta.to.shared.u64 t, %1; cvt.u32.u64 %0, t; }" : "=r"(a) : "l"(p));
    return a;
}
__device__ __forceinline__ void cp16(uint32_t s, const void* g) {
    asm volatile("cp.async.cg.shared.global [%0], [%1], 16;" :: "r"(s), "l"(g));
}
__device__ __forceinline__ void cp_commit() {
    asm volatile("cp.async.commit_group;" ::: "memory");
}
template <int N>
__device__ __forceinline__ void cp_wait() {
    asm volatile("cp.async.wait_group %0;" :: "n"(N) : "memory");
}
__device__ __forceinline__ void gdc_wait() {
    asm volatile("griddepcontrol.wait;" ::: "memory");
}
__device__ __forceinline__ void gdc_launch() {
    asm volatile("griddepcontrol.launch_dependents;");
}
__device__ __forceinline__ void ldm4(uint32_t& r0, uint32_t& r1, uint32_t& r2, uint32_t& r3,
                                     uint32_t addr) {
    asm volatile("ldmatrix.sync.aligned.m8n8.x4.shared.b16 {%0,%1,%2,%3}, [%4];"
                 : "=r"(r0), "=r"(r1), "=r"(r2), "=r"(r3) : "r"(addr));
}
__device__ __forceinline__ void ldm4t(uint32_t& r0, uint32_t& r1, uint32_t& r2, uint32_t& r3,
                                      uint32_t addr) {
    asm volatile("ldmatrix.sync.aligned.m8n8.x4.trans.shared.b16 {%0,%1,%2,%3}, [%4];"
                 : "=r"(r0), "=r"(r1), "=r"(r2), "=r"(r3) : "r"(addr));
}
__device__ __forceinline__ void mma_f16(float* d, const uint32_t* a, const uint32_t* b) {
    asm volatile(
        "mma.sync.aligned.m16n8k16.row.col.f32.f16.f16.f32 "
        "{%0,%1,%2,%3}, {%4,%5,%6,%7}, {%8,%9}, {%0,%1,%2,%3};"
        : "+f"(d[0]), "+f"(d[1]), "+f"(d[2]), "+f"(d[3])
        : "r"(a[0]), "r"(a[1]), "r"(a[2]), "r"(a[3]), "r"(b[0]), "r"(b[1]));
}
// f16-accumulate variant: d is 2x f16x2 packed regs (bit-compatible with the
// A-fragment layout of a following m16n8k16 MMA).
__device__ __forceinline__ void mma_f16h(uint32_t* d, const uint32_t* a, const uint32_t* b) {
    asm volatile(
        "mma.sync.aligned.m16n8k16.row.col.f16.f16.f16.f16 "
        "{%0,%1}, {%2,%3,%4,%5}, {%6,%7}, {%0,%1};"
        : "+r"(d[0]), "+r"(d[1])
        : "r"(a[0]), "r"(a[1]), "r"(a[2]), "r"(a[3]), "r"(b[0]), "r"(b[1]));
}
__device__ __forceinline__ uint32_t hadd2u(uint32_t a, uint32_t b) {
    uint32_t r;
    asm("add.rn.f16x2 %0, %1, %2;" : "=r"(r) : "r"(a), "r"(b));
    return r;
}
__device__ __forceinline__ uint32_t ex2h2(uint32_t a) {
    uint32_t r;
    asm("ex2.approx.f16x2 %0, %1;" : "=r"(r) : "r"(a));
    return r;
}
__device__ __forceinline__ float tanh_ap(float x) {
    float r;
    asm("tanh.approx.f32 %0, %1;" : "=f"(r) : "f"(x));
    return r;
}
__device__ __forceinline__ uint32_t packh2(float a, float b) {
    __half2 h = __floats2half2_rn(a, b);
    return *(uint32_t*)&h;
}
__device__ __forceinline__ float gelu_fast(float x) {
    float x3 = x * x * x;
    return 0.5f * x * (1.0f + tanh_ap(0.7978845608028654f * (x + 0.044715f * x3)));
}

// ---------------------------------------------------------------------------
// Combined cast: 3 weight tensors fp32->half, prior fp32 -> half*(alpha*F*log2e)
// Flat grid over float4 elements; segmented addressing.
// ---------------------------------------------------------------------------
#define SEG0 786432               // Wqkv:  1024*3072/4
#define SEG1 (SEG0 + 1048576)     // w1:    1024*4096/4
#define SEG2 (SEG1 + 1048576)     // w2:    4096*1024/4
#define SEG3 (SEG2 + 2097152)     // prior: 8*1024*1024/4
__global__ void __launch_bounds__(256)
cast_all_kernel(const float* __restrict__ wqkv, const float* __restrict__ w1,
                const float* __restrict__ w2, const float* __restrict__ prior,
                const float* __restrict__ alpha,
                __half* __restrict__ hq, __half* __restrict__ h1,
                __half* __restrict__ h2, __half* __restrict__ hp)
{
    const int i = blockIdx.x * 256 + threadIdx.x;
    const float* src;
    __half* dst;
    int li;
    float sc = 1.0f;
    if (i < SEG0)      { src = wqkv;  dst = hq; li = i; }
    else if (i < SEG1) { src = w1;    dst = h1; li = i - SEG0; }
    else if (i < SEG2) { src = w2;    dst = h2; li = i - SEG1; }
    else               { src = prior; dst = hp; li = i - SEG2; sc = alpha[0] * QSCALE; }
    float4 v = ((const float4*)src)[li];
    uint2 u;
    u.x = packh2(v.x * sc, v.y * sc);
    u.y = packh2(v.z * sc, v.w * sc);
    ((uint2*)dst)[li] = u;
}

// ---------------------------------------------------------------------------
// LayerNorm, warp-per-row.  8 rows per 256-thread block; warp-local reduce.
// ---------------------------------------------------------------------------
__global__ void __launch_bounds__(256)
ln_kernel(const float* __restrict__ x, const float* __restrict__ g,
          const float* __restrict__ bb, __half* __restrict__ out)
{
    gdc_launch();
    gdc_wait();
    const int warp = threadIdx.x >> 5, lane = threadIdx.x & 31;
    const int row = blockIdx.x * 8 + warp;
    const float4* xr = (const float4*)(x + (size_t)row * Dq);

    float4 v[8];
    float s = 0.0f, s2 = 0.0f;
#pragma unroll
    for (int t = 0; t < 8; t++) {
        v[t] = xr[lane + t * 32];
        s += v[t].x + v[t].y + v[t].z + v[t].w;
        s2 += v[t].x * v[t].x + v[t].y * v[t].y + v[t].z * v[t].z + v[t].w * v[t].w;
    }
#pragma unroll
    for (int o = 16; o; o >>= 1) {
        s += __shfl_xor_sync(0xffffffffu, s, o);
        s2 += __shfl_xor_sync(0xffffffffu, s2, o);
    }
    const float mu = s * (1.0f / Dq);
    const float var = s2 * (1.0f / Dq) - mu * mu;
    const float inv = rsqrtf(var + 1e-5f);

    __half* orow = out + (size_t)row * Dq;
#pragma unroll
    for (int t = 0; t < 8; t++) {
        const int i = (lane + t * 32) * 4;
        float4 gg = *(const float4*)&g[i];
        float4 bv = *(const float4*)&bb[i];
        uint2 u;
        u.x = packh2((v[t].x - mu) * inv * gg.x + bv.x, (v[t].y - mu) * inv * gg.y + bv.y);
        u.y = packh2((v[t].z - mu) * inv * gg.z + bv.z, (v[t].w - mu) * inv * gg.w + bv.w);
        *(uint2*)&orow[i] = u;
    }
}

// ---------------------------------------------------------------------------
// Flash attention, half2-domain softmax.
// S accumulated in f16 (packed layout == next MMA's A fragments);
// P = ex2.f16x2(S + pah);  l = P @ ones via fp32-accum MMA (exact, no shfl).
// grid = (N/128, B*H), 256 threads.
// ---------------------------------------------------------------------------
__global__ void __launch_bounds__(256, 1)
flash_kernel(const __half* __restrict__ qkv,
             const __half* __restrict__ pah,
             const float* __restrict__ x,
             float* __restrict__ s1)
{
    constexpr int LDR = 72;
    constexpr int TH = 128 * LDR;
    extern __shared__ __half sm[];
    const uint32_t ub = smem_u32(sm);

    const int tid = threadIdx.x;
    const int lane = tid & 31;
    const int wid = tid >> 5;
    const int gid = lane >> 2, tig = lane & 3;

    const int qt = blockIdx.x;
    const int bh = blockIdx.y;
    const int b = bh >> 4, h = bh & 15;
    const int q0 = qt * 128;

    const __half* qbase = qkv + (size_t)b * Nq * (3 * Dq) + (size_t)h * 64;
    const __half* kbase = qbase + Dq;
    const __half* vbase = qbase + 2 * Dq;

    gdc_wait();

    auto load_q = [&]() {
#pragma unroll
        for (int t = 0; t < 4; t++) {
            int id = tid + t * 256;
            int r = id >> 3, j = id & 7;
            cp16(ub + (uint32_t)(r * LDR + j * 8) * 2u,
                 qbase + (size_t)(q0 + r) * (3 * Dq) + j * 8);
        }
    };
    auto load_kv = [&](int i) {
        const int kv0 = i * 128;
        const uint32_t sk = ub + (uint32_t)(TH * (1 + 2 * (i & 1))) * 2u;
        const uint32_t sv = sk + (uint32_t)TH * 2u;
#pragma unroll
        for (int t = 0; t < 4; t++) {
            int id = tid + t * 256;
            int r = id >> 3, j = id & 7;
            cp16(sk + (uint32_t)(r * LDR + j * 8) * 2u,
                 kbase + (size_t)(kv0 + r) * (3 * Dq) + j * 8);
        }
#pragma unroll
        for (int t = 0; t < 4; t++) {
            int id = tid + t * 256;
            int r = id >> 3, j = id & 7;
            cp16(sv + (uint32_t)(r * LDR + j * 8) * 2u,
                 vbase + (size_t)(kv0 + r) * (3 * Dq) + j * 8);
        }
    };

    load_q();
    load_kv(0);
    cp_commit();

    const uint32_t qa_off = (uint32_t)((wid * 16 + (lane & 15)) * LDR + ((lane >> 4) << 3));
    const uint32_t kb_off = (uint32_t)(((lane & 7) + ((lane >> 4) << 3)) * LDR +
                                       (((lane >> 3) & 1) << 3));
    const uint32_t vb_off = (uint32_t)(((lane & 7) + (((lane >> 3) & 1) << 3)) * LDR +
                                       ((lane >> 4) << 3));

    uint32_t qa[4][4];
    float oacc[8][4];
#pragma unroll
    for (int t = 0; t < 8; t++)
#pragma unroll
        for (int q = 0; q < 4; q++) oacc[t][q] = 0.0f;
    float lacc[4] = {0.0f, 0.0f, 0.0f, 0.0f};
    const uint32_t ONES = 0x3C003C00u;   // half2 {1.0, 1.0}
    const uint32_t b_ones[2] = {ONES, ONES};

    const __half* prh0 = pah + (size_t)b * Nq * Nq + (size_t)(q0 + wid * 16 + gid) * Nq;
    const __half* prh1 = prh0 + 8 * Nq;

    for (int i = 0; i < 8; i++) {
        cp_wait<0>();
        __syncthreads();
        if (i == 0) {
#pragma unroll
            for (int ks = 0; ks < 4; ks++)
                ldm4(qa[ks][0], qa[ks][1], qa[ks][2], qa[ks][3],
                     ub + (qa_off + (uint32_t)(ks * 16)) * 2u);
        }
        if (i < 7) {
            load_kv(i + 1);
            cp_commit();
        }

        const uint32_t sk = ub + (uint32_t)(TH * (1 + 2 * (i & 1))) * 2u;
        const uint32_t sv = sk + (uint32_t)TH * 2u;

        // ---- S = Q K^T  (f16 accumulators, packed) ----
        uint32_t s2[16][2];
#pragma unroll
        for (int j = 0; j < 16; j++) { s2[j][0] = 0u; s2[j][1] = 0u; }
#pragma unroll
        for (int ks = 0; ks < 4; ks++) {
#pragma unroll
            for (int nb = 0; nb < 8; nb++) {
                uint32_t r0, r1, r2, r3;
                ldm4(r0, r1, r2, r3,
                     sk + (kb_off + (uint32_t)(nb * 16 * LDR + ks * 16)) * 2u);
                uint32_t b01[2] = {r0, r1}, b23[2] = {r2, r3};
                mma_f16h(s2[2 * nb + 0], qa[ks], b01);
                mma_f16h(s2[2 * nb + 1], qa[ks], b23);
            }
        }

        // ---- P = 2^(S + pah)  (half2 domain) ----
        const int kvc = i * 128 + tig * 2;
#pragma unroll
        for (int j = 0; j < 16; j++) {
            uint32_t pp0 = *(const uint32_t*)(prh0 + kvc + j * 8);
            uint32_t pp1 = *(const uint32_t*)(prh1 + kvc + j * 8);
            s2[j][0] = ex2h2(hadd2u(s2[j][0], pp0));
            s2[j][1] = ex2h2(hadd2u(s2[j][1], pp1));
        }

        // ---- O += P V ;  l += P @ ones (fp32 tensor accum) ----
#pragma unroll
        for (int ks = 0; ks < 8; ks++) {
            uint32_t pa[4] = {s2[2 * ks][0], s2[2 * ks][1],
                              s2[2 * ks + 1][0], s2[2 * ks + 1][1]};
            mma_f16(lacc, pa, b_ones);
#pragma unroll
            for (int c = 0; c < 4; c++) {
                uint32_t r0, r1, r2, r3;
                ldm4t(r0, r1, r2, r3,
                      sv + (vb_off + (uint32_t)(ks * 16 * LDR + c * 16)) * 2u);
                uint32_t b01[2] = {r0, r1}, b23[2] = {r2, r3};
                mma_f16(oacc[2 * c + 0], pa, b01);
                mma_f16(oacc[2 * c + 1], pa, b23);
            }
        }
    }

    gdc_launch();

    // lacc: cols identical; lacc[0] = row gid sum, lacc[2] = row gid+8 sum
    const float inv0 = 1.0f / lacc[0], inv1 = 1.0f / lacc[2];

    const int gr0 = q0 + wid * 16 + gid;
    const size_t o0 = (size_t)b * Nq * Dq + (size_t)gr0 * Dq + h * 64 + tig * 2;
    const size_t o1 = o0 + (size_t)8 * Dq;
#pragma unroll
    for (int t = 0; t < 8; t++) {
        float2 x0 = *(const float2*)(x + o0 + t * 8);
        float2 x1 = *(const float2*)(x + o1 + t * 8);
        float2 w0 = make_float2(oacc[t][0] * inv0 + x0.x, oacc[t][1] * inv0 + x0.y);
        float2 w1 = make_float2(oacc[t][2] * inv1 + x1.x, oacc[t][3] * inv1 + x1.y);
        *(float2*)(s1 + o0 + t * 8) = w0;
        *(float2*)(s1 + o1 + t * 8) = w1;
    }
}

// ---------------------------------------------------------------------------
// fp16 mma.sync GEMM (fp32 accum).  BM=128, BN=256, BK=64, 4-stage cp.async.
// A [M,K] half K-major; B [K,N] half row-major (ldmatrix.trans fragments).
// 8 warps 2(M)x4(N); warp tile 64x64.  PDL: B prologue before gdc_wait;
// launch_dependents after mainloop so the next kernel overlaps the epilogue.
// ---------------------------------------------------------------------------
template <int EPI, typename CT>
__global__ void __launch_bounds__(256, 1)
mma_gemm(const __half* __restrict__ A, int lda,
         const __half* __restrict__ B, int ldb,
         CT* __restrict__ C, int ldc, int K,
         const float* __restrict__ e0, const float* __restrict__ e1)
{
    constexpr int BM = 128;
    constexpr int BN = 256;
    constexpr int BK = 64;
    constexpr int S = 4;
    constexpr int LDRA = 72;
    constexpr int LDRB = BN + 8;
    constexpr int AH = BM * LDRA;
    constexpr int BH = BK * LDRB;
    constexpr int STGH = AH + BH;
    constexpr int MF = 4;
    constexpr int NC = 4;

    extern __shared__ __half smh[];
    const uint32_t ubase = smem_u32(smh);

    const int tid = threadIdx.x;
    const int lane = tid & 31;
    const int wid = tid >> 5;
    const int wm = wid >> 2, wn = wid & 3;
    const int gid = lane >> 2, tig = lane & 3;

    const int row0 = blockIdx.y * BM;
    const int col0 = blockIdx.x * BN;
    const int niter = K / BK;

    const uint32_t a_off = (uint32_t)((wm * 64 + (lane & 15)) * LDRA + ((lane >> 4) << 3));
    const uint32_t b_off = (uint32_t)(((lane & 7) + (((lane >> 3) & 1) << 3)) * LDRB +
                                      wn * 64 + ((lane >> 4) << 3));

    auto load_a = [&](int it) {
        const int k0 = it * BK;
        const uint32_t sa = ubase + (uint32_t)((it % S) * STGH) * 2u;
#pragma unroll
        for (int t = 0; t < 4; t++) {
            int id = tid + t * 256;
            int r = id >> 3, j = id & 7;
            cp16(sa + (uint32_t)r * 144u + (uint32_t)j * 16u,
                 A + (size_t)(row0 + r) * lda + k0 + j * 8);
        }
    };
    auto load_b = [&](int it) {
        const int k0 = it * BK;
        const uint32_t sb = ubase + (uint32_t)((it % S) * STGH + AH) * 2u;
#pragma unroll
        for (int t = 0; t < 8; t++) {
            int id = tid + t * 256;
            int r = id >> 5, j = id & 31;
            cp16(sb + (uint32_t)r * (LDRB * 2) + (uint32_t)j * 16u,
                 B + (size_t)(k0 + r) * ldb + col0 + j * 8);
        }
    };

    // B prologue BEFORE the dependency wait (weights ready at graph start)
#pragma unroll
    for (int it = 0; it < S - 1; it++) load_b(it);
    gdc_wait();
#pragma unroll
    for (int it = 0; it < S - 1; it++) {
        load_a(it);
        cp_commit();
    }

    float acc[MF][8][4];
#pragma unroll
    for (int mf = 0; mf < MF; mf++)
#pragma unroll
        for (int nf = 0; nf < 8; nf++)
#pragma unroll
            for (int q = 0; q < 4; q++) acc[mf][nf][q] = 0.0f;

    for (int i = 0; i < niter; i++) {
        cp_wait<S - 2>();
        __syncthreads();
        if (i + S - 1 < niter) {
            load_b(i + S - 1);
            load_a(i + S - 1);
        }
        cp_commit();

        const uint32_t sa = ubase + (uint32_t)((i % S) * STGH) * 2u;
        const uint32_t sb = ubase + (uint32_t)((i % S) * STGH + AH) * 2u;

#pragma unroll
        for (int ks = 0; ks < BK / 16; ks++) {
            uint32_t a[MF][4], b[NC][4];
#pragma unroll
            for (int mf = 0; mf < MF; mf++)
                ldm4(a[mf][0], a[mf][1], a[mf][2], a[mf][3],
                     sa + (a_off + (uint32_t)(mf * 16 * LDRA + ks * 16)) * 2u);
#pragma unroll
            for (int c = 0; c < NC; c++)
                ldm4t(b[c][0], b[c][1], b[c][2], b[c][3],
                      sb + (b_off + (uint32_t)(ks * 16 * LDRB + c * 16)) * 2u);
#pragma unroll
            for (int mf = 0; mf < MF; mf++)
#pragma unroll
                for (int c = 0; c < NC; c++) {
                    mma_f16(acc[mf][2 * c + 0], a[mf], &b[c][0]);
                    mma_f16(acc[mf][2 * c + 1], a[mf], &b[c][2]);
                }
        }
    }

    gdc_launch();

#pragma unroll
    for (int mf = 0; mf < MF; mf++) {
        const int gr0 = row0 + wm * 64 + mf * 16 + gid;
#pragma unroll
        for (int nf = 0; nf < 8; nf++) {
            const int gc = col0 + wn * 64 + nf * 8 + tig * 2;
#pragma unroll
            for (int half_ = 0; half_ < 2; half_++) {
                const int gr = gr0 + half_ * 8;
                float v0 = acc[mf][nf][half_ * 2 + 0];
                float v1 = acc[mf][nf][half_ * 2 + 1];
                float o0, o1;
                if constexpr (EPI == EPI_QKV) {
                    o0 = v0 + e0[gc]; o1 = v1 + e0[gc + 1];
                    if (gc < Dq) { o0 *= QSCALE; o1 *= QSCALE; }
                } else if constexpr (EPI == EPI_GELU) {
                    o0 = gelu_fast(v0 + e0[gc]); o1 = gelu_fast(v1 + e0[gc + 1]);
                } else {  // EPI_RES
                    float2 rr = *(const float2*)&e1[(size_t)gr * ldc + gc];
                    o0 = v0 + e0[gc] + rr.x; o1 = v1 + e0[gc + 1] + rr.y;
                }
                if constexpr (sizeof(CT) == 2) {
                    *(__half2*)&C[(size_t)gr * ldc + gc] = __floats2half2_rn(o0, o1);
                } else {
                    *(float2*)&C[(size_t)gr * ldc + gc] = make_float2(o0, o1);
                }
            }
        }
    }
}

// ---------------------------------------------------------------------------
// launch
// ---------------------------------------------------------------------------
extern "C" void kernel_launch(void* const* d_in, const int* in_sizes, int n_in,
                              void* d_out, int out_size)
{
    const float* x     = (const float*)d_in[0];
    const float* prior = (const float*)d_in[1];
    const float* Wqkv  = (const float*)d_in[2];
    const float* bqkv  = (const float*)d_in[3];
    const float* alpha = (const float*)d_in[4];
    const float* ln1_g = (const float*)d_in[5];
    const float* ln1_b = (const float*)d_in[6];
    const float* ln2_g = (const float*)d_in[7];
    const float* ln2_b = (const float*)d_in[8];
    const float* w1    = (const float*)d_in[9];
    const float* b1    = (const float*)d_in[10];
    const float* w2    = (const float*)d_in[11];
    const float* b2    = (const float*)d_in[12];
    float* out = (float*)d_out;

    __half *zp, *qkvp, *h1p, *whqkv, *wh1, *wh2, *pahp;
    float* s1p;
    cudaGetSymbolAddress((void**)&zp, g_z);
    cudaGetSymbolAddress((void**)&qkvp, g_qkv);
    cudaGetSymbolAddress((void**)&s1p, g_s1);
    cudaGetSymbolAddress((void**)&h1p, g_h1);
    cudaGetSymbolAddress((void**)&whqkv, g_whqkv);
    cudaGetSymbolAddress((void**)&wh1, g_wh1);
    cudaGetSymbolAddress((void**)&wh2, g_wh2);
    cudaGetSymbolAddress((void**)&pahp, g_pah);

    const int smem_g  = 4 * (128 * 72 + 64 * 264) * 2;   // 208896
    const int smem_fa = 5 * 128 * 72 * 2;                // 92160
    cudaFuncSetAttribute(mma_gemm<EPI_QKV, __half>,  cudaFuncAttributeMaxDynamicSharedMemorySize, smem_g);
    cudaFuncSetAttribute(mma_gemm<EPI_GELU, __half>, cudaFuncAttributeMaxDynamicSharedMemorySize, smem_g);
    cudaFuncSetAttribute(mma_gemm<EPI_RES, float>,   cudaFuncAttributeMaxDynamicSharedMemorySize, smem_g);
    cudaFuncSetAttribute(flash_kernel, cudaFuncAttributeMaxDynamicSharedMemorySize, smem_fa);

    const int rows = Bq * Nq;  // 8192

    cudaLaunchAttribute pattr[1];
    pattr[0].id = cudaLaunchAttributeProgrammaticStreamSerialization;
    pattr[0].val.programmaticStreamSerializationAllowed = 1;

    // 0) all casts in one kernel (weights + pre-scaled half prior)
    cast_all_kernel<<<SEG3 / 256, 256>>>(Wqkv, w1, w2, prior, alpha,
                                         whqkv, wh1, wh2, pahp);

    // 1) z = LN1(x)
    {
        cudaLaunchConfig_t cfg{};
        cfg.gridDim = dim3(rows / 8); cfg.blockDim = dim3(256);
        cfg.attrs = pattr; cfg.numAttrs = 1;
        cudaLaunchKernelEx(&cfg, ln_kernel, x, ln1_g, ln1_b, (__half*)zp);
    }
    // 2) qkv = z @ Wqkv + bqkv  (q pre-scaled by F*log2e)
    {
        cudaLaunchConfig_t cfg{};
        cfg.gridDim = dim3(3 * Dq / 256, rows / 128); cfg.blockDim = dim3(256);
        cfg.dynamicSmemBytes = smem_g; cfg.attrs = pattr; cfg.numAttrs = 1;
        cudaLaunchKernelEx(&cfg, mma_gemm<EPI_QKV, __half>,
                           (const __half*)zp, (int)Dq, (const __half*)whqkv, (int)(3 * Dq),
                           (__half*)qkvp, (int)(3 * Dq), (int)Dq, bqkv, (const float*)nullptr);
    }
    // 3) fused attention
    {
        cudaLaunchConfig_t cfg{};
        cfg.gridDim = dim3(Nq / 128, Bq * Hq); cfg.blockDim = dim3(256);
        cfg.dynamicSmemBytes = smem_fa; cfg.attrs = pattr; cfg.numAttrs = 1;
        cudaLaunchKernelEx(&cfg, flash_kernel,
                           (const __half*)qkvp, (const __half*)pahp, x, (float*)s1p);
    }
    // 4) z = LN2(s1)
    {
        cudaLaunchConfig_t cfg{};
        cfg.gridDim = dim3(rows / 8); cfg.blockDim = dim3(256);
        cfg.attrs = pattr; cfg.numAttrs = 1;
        cudaLaunchKernelEx(&cfg, ln_kernel, (const float*)s1p, ln2_g, ln2_b, (__half*)zp);
    }
    // 5) h1 = gelu(z @ w1 + b1)
    {
        cudaLaunchConfig_t cfg{};
        cfg.gridDim = dim3(DFFq / 256, rows / 128); cfg.blockDim = dim3(256);
        cfg.dynamicSmemBytes = smem_g; cfg.attrs = pattr; cfg.numAttrs = 1;
        cudaLaunchKernelEx(&cfg, mma_gemm<EPI_GELU, __half>,
                           (const __half*)zp, (int)Dq, (const __half*)wh1, (int)DFFq,
                           (__half*)h1p, (int)DFFq, (int)Dq, b1, (const float*)nullptr);
    }
    // 6) out = s1 + h1 @ w2 + b2
    {
        cudaLaunchConfig_t cfg{};
        cfg.gridDim = dim3(Dq / 256, rows / 128); cfg.blockDim = dim3(256);
        cfg.dynamicSmemBytes = smem_g; cfg.attrs = pattr; cfg.numAttrs = 1;
        cudaLaunchKernelEx(&cfg, mma_gemm<EPI_RES, float>,
                           (const __half*)h1p, (int)DFFq, (const __half*)wh2, (int)Dq,
                           out, (int)Dq, (int)DFFq, b2, (const float*)s1p);
    }
}

// round 11
// speedup vs baseline: 1.0417x; 1.0417x over previous
#include <cuda_runtime.h>
#include <cuda_fp16.h>
#include <math.h>
#include <stdint.h>

// ---------------- problem constants ----------------
#define Bq   8
#define Nq   1024
#define Dq   1024
#define Hq   16
#define DFFq 4096
#define FACTORq 0.125f
#define QSCALE 0.18033688f   // 0.125 * log2(e)

// ---------------- scratch (device globals) ----------------
__device__ __half g_z[(size_t)Bq * Nq * Dq];
__device__ __half g_qkv[(size_t)Bq * Nq * 3 * Dq];
__device__ float  g_s1[(size_t)Bq * Nq * Dq];
__device__ __half g_h1[(size_t)Bq * Nq * DFFq];
__device__ __half g_whqkv[(size_t)Dq * 3 * Dq];
__device__ __half g_wh1[(size_t)Dq * DFFq];
__device__ __half g_wh2[(size_t)DFFq * Dq];
__device__ __half g_pah[(size_t)Bq * Nq * Nq];   // prior * alpha*F*log2e, half

#define EPI_QKV    0
#define EPI_GELU   1
#define EPI_RES    2

// ---------------- PTX helpers (sm_90+ generic ISA only) ----------------
__device__ __forceinline__ uint32_t smem_u32(const void* p) {
    uint32_t a;
    asm("{ .reg .u64 t; cvta.to.shared.u64 t, %1; cvt.u32.u64 %0, t; }" : "=r"(a) : "l"(p));
    return a;
}
__device__ __forceinline__ void cp16(uint32_t s, const void* g) {
    asm volatile("cp.async.cg.shared.global [%0], [%1], 16;" :: "r"(s), "l"(g));
}
__device__ __forceinline__ void cp_commit() {
    asm volatile("cp.async.commit_group;" ::: "memory");
}
template <int N>
__device__ __forceinline__ void cp_wait() {
    asm volatile("cp.async.wait_group %0;" :: "n"(N) : "memory");
}
__device__ __forceinline__ void gdc_wait() {
    asm volatile("griddepcontrol.wait;" ::: "memory");
}
__device__ __forceinline__ void gdc_launch() {
    asm volatile("griddepcontrol.launch_dependents;");
}
__device__ __forceinline__ void ldm4(uint32_t& r0, uint32_t& r1, uint32_t& r2, uint32_t& r3,
                                     uint32_t addr) {
    asm volatile("ldmatrix.sync.aligned.m8n8.x4.shared.b16 {%0,%1,%2,%3}, [%4];"
                 : "=r"(r0), "=r"(r1), "=r"(r2), "=r"(r3) : "r"(addr));
}
__device__ __forceinline__ void ldm4t(uint32_t& r0, uint32_t& r1, uint32_t& r2, uint32_t& r3,
                                      uint32_t addr) {
    asm volatile("ldmatrix.sync.aligned.m8n8.x4.trans.shared.b16 {%0,%1,%2,%3}, [%4];"
                 : "=r"(r0), "=r"(r1), "=r"(r2), "=r"(r3) : "r"(addr));
}
__device__ __forceinline__ void mma_f16(float* d, const uint32_t* a, const uint32_t* b) {
    asm volatile(
        "mma.sync.aligned.m16n8k16.row.col.f32.f16.f16.f32 "
        "{%0,%1,%2,%3}, {%4,%5,%6,%7}, {%8,%9}, {%0,%1,%2,%3};"
        : "+f"(d[0]), "+f"(d[1]), "+f"(d[2]), "+f"(d[3])
        : "r"(a[0]), "r"(a[1]), "r"(a[2]), "r"(a[3]), "r"(b[0]), "r"(b[1]));
}
// f16-accumulate variant: d is 2x f16x2 packed regs (bit-compatible with the
// A-fragment layout of a following m16n8k16 MMA).
__device__ __forceinline__ void mma_f16h(uint32_t* d, const uint32_t* a, const uint32_t* b) {
    asm volatile(
        "mma.sync.aligned.m16n8k16.row.col.f16.f16.f16.f16 "
        "{%0,%1}, {%2,%3,%4,%5}, {%6,%7}, {%0,%1};"
        : "+r"(d[0]), "+r"(d[1])
        : "r"(a[0]), "r"(a[1]), "r"(a[2]), "r"(a[3]), "r"(b[0]), "r"(b[1]));
}
__device__ __forceinline__ uint32_t hadd2u(uint32_t a, uint32_t b) {
    uint32_t r;
    asm("add.rn.f16x2 %0, %1, %2;" : "=r"(r) : "r"(a), "r"(b));
    return r;
}
__device__ __forceinline__ uint32_t ex2h2(uint32_t a) {
    uint32_t r;
    asm("ex2.approx.f16x2 %0, %1;" : "=r"(r) : "r"(a));
    return r;
}
__device__ __forceinline__ float tanh_ap(float x) {
    float r;
    asm("tanh.approx.f32 %0, %1;" : "=f"(r) : "f"(x));
    return r;
}
__device__ __forceinline__ uint32_t packh2(float a, float b) {
    __half2 h = __floats2half2_rn(a, b);
    return *(uint32_t*)&h;
}
__device__ __forceinline__ float gelu_fast(float x) {
    float x3 = x * x * x;
    return 0.5f * x * (1.0f + tanh_ap(0.7978845608028654f * (x + 0.044715f * x3)));
}

// ---------------------------------------------------------------------------
// Combined cast: 3 weight tensors fp32->half, prior fp32 -> half*(alpha*F*log2e)
// ---------------------------------------------------------------------------
#define SEG0 786432               // Wqkv:  1024*3072/4
#define SEG1 (SEG0 + 1048576)     // w1:    1024*4096/4
#define SEG2 (SEG1 + 1048576)     // w2:    4096*1024/4
#define SEG3 (SEG2 + 2097152)     // prior: 8*1024*1024/4
__global__ void __launch_bounds__(256)
cast_all_kernel(const float* __restrict__ wqkv, const float* __restrict__ w1,
                const float* __restrict__ w2, const float* __restrict__ prior,
                const float* __restrict__ alpha,
                __half* __restrict__ hq, __half* __restrict__ h1,
                __half* __restrict__ h2, __half* __restrict__ hp)
{
    const int i = blockIdx.x * 256 + threadIdx.x;
    const float* src;
    __half* dst;
    int li;
    float sc = 1.0f;
    if (i < SEG0)      { src = wqkv;  dst = hq; li = i; }
    else if (i < SEG1) { src = w1;    dst = h1; li = i - SEG0; }
    else if (i < SEG2) { src = w2;    dst = h2; li = i - SEG1; }
    else               { src = prior; dst = hp; li = i - SEG2; sc = alpha[0] * QSCALE; }
    float4 v = ((const float4*)src)[li];
    uint2 u;
    u.x = packh2(v.x * sc, v.y * sc);
    u.y = packh2(v.z * sc, v.w * sc);
    ((uint2*)dst)[li] = u;
}

// ---------------------------------------------------------------------------
// LayerNorm, warp-per-row.
// ---------------------------------------------------------------------------
__global__ void __launch_bounds__(256)
ln_kernel(const float* __restrict__ x, const float* __restrict__ g,
          const float* __restrict__ bb, __half* __restrict__ out)
{
    gdc_launch();
    gdc_wait();
    const int warp = threadIdx.x >> 5, lane = threadIdx.x & 31;
    const int row = blockIdx.x * 8 + warp;
    const float4* xr = (const float4*)(x + (size_t)row * Dq);

    float4 v[8];
    float s = 0.0f, s2 = 0.0f;
#pragma unroll
    for (int t = 0; t < 8; t++) {
        v[t] = xr[lane + t * 32];
        s += v[t].x + v[t].y + v[t].z + v[t].w;
        s2 += v[t].x * v[t].x + v[t].y * v[t].y + v[t].z * v[t].z + v[t].w * v[t].w;
    }
#pragma unroll
    for (int o = 16; o; o >>= 1) {
        s += __shfl_xor_sync(0xffffffffu, s, o);
        s2 += __shfl_xor_sync(0xffffffffu, s2, o);
    }
    const float mu = s * (1.0f / Dq);
    const float var = s2 * (1.0f / Dq) - mu * mu;
    const float inv = rsqrtf(var + 1e-5f);

    __half* orow = out + (size_t)row * Dq;
#pragma unroll
    for (int t = 0; t < 8; t++) {
        const int i = (lane + t * 32) * 4;
        float4 gg = *(const float4*)&g[i];
        float4 bv = *(const float4*)&bb[i];
        uint2 u;
        u.x = packh2((v[t].x - mu) * inv * gg.x + bv.x, (v[t].y - mu) * inv * gg.y + bv.y);
        u.y = packh2((v[t].z - mu) * inv * gg.z + bv.z, (v[t].w - mu) * inv * gg.w + bv.w);
        *(uint2*)&orow[i] = u;
    }
}

// ---------------------------------------------------------------------------
// Flash attention, half2-domain softmax, 2 CTAs/SM.
// kv tile processed in two nb-halves to halve live registers (s2: 16 regs).
// grid = (N/128, B*H), 256 threads.
// ---------------------------------------------------------------------------
__global__ void __launch_bounds__(256, 2)
flash_kernel(const __half* __restrict__ qkv,
             const __half* __restrict__ pah,
             const float* __restrict__ x,
             float* __restrict__ s1)
{
    constexpr int LDR = 72;
    constexpr int TH = 128 * LDR;
    extern __shared__ __half sm[];
    const uint32_t ub = smem_u32(sm);

    const int tid = threadIdx.x;
    const int lane = tid & 31;
    const int wid = tid >> 5;
    const int gid = lane >> 2, tig = lane & 3;

    const int qt = blockIdx.x;
    const int bh = blockIdx.y;
    const int b = bh >> 4, h = bh & 15;
    const int q0 = qt * 128;

    const __half* qbase = qkv + (size_t)b * Nq * (3 * Dq) + (size_t)h * 64;
    const __half* kbase = qbase + Dq;
    const __half* vbase = qbase + 2 * Dq;

    gdc_wait();

    auto load_q = [&]() {
#pragma unroll
        for (int t = 0; t < 4; t++) {
            int id = tid + t * 256;
            int r = id >> 3, j = id & 7;
            cp16(ub + (uint32_t)(r * LDR + j * 8) * 2u,
                 qbase + (size_t)(q0 + r) * (3 * Dq) + j * 8);
        }
    };
    auto load_kv = [&](int i) {
        const int kv0 = i * 128;
        const uint32_t sk = ub + (uint32_t)(TH * (1 + 2 * (i & 1))) * 2u;
        const uint32_t sv = sk + (uint32_t)TH * 2u;
#pragma unroll
        for (int t = 0; t < 4; t++) {
            int id = tid + t * 256;
            int r = id >> 3, j = id & 7;
            cp16(sk + (uint32_t)(r * LDR + j * 8) * 2u,
                 kbase + (size_t)(kv0 + r) * (3 * Dq) + j * 8);
        }
#pragma unroll
        for (int t = 0; t < 4; t++) {
            int id = tid + t * 256;
            int r = id >> 3, j = id & 7;
            cp16(sv + (uint32_t)(r * LDR + j * 8) * 2u,
                 vbase + (size_t)(kv0 + r) * (3 * Dq) + j * 8);
        }
    };

    load_q();
    load_kv(0);
    cp_commit();

    const uint32_t qa_off = (uint32_t)((wid * 16 + (lane & 15)) * LDR + ((lane >> 4) << 3));
    const uint32_t kb_off = (uint32_t)(((lane & 7) + ((lane >> 4) << 3)) * LDR +
                                       (((lane >> 3) & 1) << 3));
    const uint32_t vb_off = (uint32_t)(((lane & 7) + (((lane >> 3) & 1) << 3)) * LDR +
                                       ((lane >> 4) << 3));

    uint32_t qa[4][4];
    float oacc[8][4];
#pragma unroll
    for (int t = 0; t < 8; t++)
#pragma unroll
        for (int q = 0; q < 4; q++) oacc[t][q] = 0.0f;
    float lacc[4] = {0.0f, 0.0f, 0.0f, 0.0f};
    const uint32_t ONES = 0x3C003C00u;
    const uint32_t b_ones[2] = {ONES, ONES};

    const __half* prh0 = pah + (size_t)b * Nq * Nq + (size_t)(q0 + wid * 16 + gid) * Nq;
    const __half* prh1 = prh0 + 8 * Nq;

    for (int i = 0; i < 8; i++) {
        cp_wait<0>();
        __syncthreads();
        if (i == 0) {
#pragma unroll
            for (int ks = 0; ks < 4; ks++)
                ldm4(qa[ks][0], qa[ks][1], qa[ks][2], qa[ks][3],
                     ub + (qa_off + (uint32_t)(ks * 16)) * 2u);
        }
        if (i < 7) {
            load_kv(i + 1);
            cp_commit();
        }

        const uint32_t sk = ub + (uint32_t)(TH * (1 + 2 * (i & 1))) * 2u;
        const uint32_t sv = sk + (uint32_t)TH * 2u;

        // process kv tile in two halves of 64 columns (4 nb blocks each)
#pragma unroll
        for (int h2 = 0; h2 < 2; h2++) {
            // ---- S = Q K^T  (f16 accumulators, packed; 8 fragments) ----
            uint32_t s2[8][2];
#pragma unroll
            for (int j = 0; j < 8; j++) { s2[j][0] = 0u; s2[j][1] = 0u; }
#pragma unroll
            for (int ks = 0; ks < 4; ks++) {
#pragma unroll
                for (int nb = 0; nb < 4; nb++) {
                    uint32_t r0, r1, r2, r3;
                    ldm4(r0, r1, r2, r3,
                         sk + (kb_off + (uint32_t)(((h2 * 4 + nb) * 16) * LDR + ks * 16)) * 2u);
                    uint32_t b01[2] = {r0, r1}, b23[2] = {r2, r3};
                    mma_f16h(s2[2 * nb + 0], qa[ks], b01);
                    mma_f16h(s2[2 * nb + 1], qa[ks], b23);
                }
            }

            // ---- P = 2^(S + pah) ----
            const int kvc = i * 128 + h2 * 64 + tig * 2;
#pragma unroll
            for (int j = 0; j < 8; j++) {
                uint32_t pp0 = *(const uint32_t*)(prh0 + kvc + j * 8);
                uint32_t pp1 = *(const uint32_t*)(prh1 + kvc + j * 8);
                s2[j][0] = ex2h2(hadd2u(s2[j][0], pp0));
                s2[j][1] = ex2h2(hadd2u(s2[j][1], pp1));
            }

            // ---- O += P V ;  l += P @ ones ----
#pragma unroll
            for (int ks = 0; ks < 4; ks++) {
                uint32_t pa[4] = {s2[2 * ks][0], s2[2 * ks][1],
                                  s2[2 * ks + 1][0], s2[2 * ks + 1][1]};
                mma_f16(lacc, pa, b_ones);
#pragma unroll
                for (int c = 0; c < 4; c++) {
                    uint32_t r0, r1, r2, r3;
                    ldm4t(r0, r1, r2, r3,
                          sv + (vb_off + (uint32_t)(((h2 * 4 + ks) * 16) * LDR + c * 16)) * 2u);
                    uint32_t b01[2] = {r0, r1}, b23[2] = {r2, r3};
                    mma_f16(oacc[2 * c + 0], pa, b01);
                    mma_f16(oacc[2 * c + 1], pa, b23);
                }
            }
        }
    }

    gdc_launch();

    const float inv0 = 1.0f / lacc[0], inv1 = 1.0f / lacc[2];

    const int gr0 = q0 + wid * 16 + gid;
    const size_t o0 = (size_t)b * Nq * Dq + (size_t)gr0 * Dq + h * 64 + tig * 2;
    const size_t o1 = o0 + (size_t)8 * Dq;
#pragma unroll
    for (int t = 0; t < 8; t++) {
        float2 x0 = *(const float2*)(x + o0 + t * 8);
        float2 x1 = *(const float2*)(x + o1 + t * 8);
        float2 w0 = make_float2(oacc[t][0] * inv0 + x0.x, oacc[t][1] * inv0 + x0.y);
        float2 w1 = make_float2(oacc[t][2] * inv1 + x1.x, oacc[t][3] * inv1 + x1.y);
        *(float2*)(s1 + o0 + t * 8) = w0;
        *(float2*)(s1 + o1 + t * 8) = w1;
    }
}

// ---------------------------------------------------------------------------
// fp16 mma.sync GEMM (fp32 accum).  BM=128, BN=256, BK=64, 4-stage cp.async.
// A [M,K] half K-major; B [K,N] half row-major (ldmatrix.trans fragments).
// 8 warps 2(M)x4(N); warp tile 64x64.  PDL as in R9/R10.
// ---------------------------------------------------------------------------
template <int EPI, typename CT>
__global__ void __launch_bounds__(256, 1)
mma_gemm(const __half* __restrict__ A, int lda,
         const __half* __restrict__ B, int ldb,
         CT* __restrict__ C, int ldc, int K,
         const float* __restrict__ e0, const float* __restrict__ e1)
{
    constexpr int BM = 128;
    constexpr int BN = 256;
    constexpr int BK = 64;
    constexpr int S = 4;
    constexpr int LDRA = 72;
    constexpr int LDRB = BN + 8;
    constexpr int AH = BM * LDRA;
    constexpr int BH = BK * LDRB;
    constexpr int STGH = AH + BH;
    constexpr int MF = 4;
    constexpr int NC = 4;

    extern __shared__ __half smh[];
    const uint32_t ubase = smem_u32(smh);

    const int tid = threadIdx.x;
    const int lane = tid & 31;
    const int wid = tid >> 5;
    const int wm = wid >> 2, wn = wid & 3;
    const int gid = lane >> 2, tig = lane & 3;

    const int row0 = blockIdx.y * BM;
    const int col0 = blockIdx.x * BN;
    const int niter = K / BK;

    const uint32_t a_off = (uint32_t)((wm * 64 + (lane & 15)) * LDRA + ((lane >> 4) << 3));
    const uint32_t b_off = (uint32_t)(((lane & 7) + (((lane >> 3) & 1) << 3)) * LDRB +
                                      wn * 64 + ((lane >> 4) << 3));

    auto load_a = [&](int it) {
        const int k0 = it * BK;
        const uint32_t sa = ubase + (uint32_t)((it % S) * STGH) * 2u;
#pragma unroll
        for (int t = 0; t < 4; t++) {
            int id = tid + t * 256;
            int r = id >> 3, j = id & 7;
            cp16(sa + (uint32_t)r * 144u + (uint32_t)j * 16u,
                 A + (size_t)(row0 + r) * lda + k0 + j * 8);
        }
    };
    auto load_b = [&](int it) {
        const int k0 = it * BK;
        const uint32_t sb = ubase + (uint32_t)((it % S) * STGH + AH) * 2u;
#pragma unroll
        for (int t = 0; t < 8; t++) {
            int id = tid + t * 256;
            int r = id >> 5, j = id & 31;
            cp16(sb + (uint32_t)r * (LDRB * 2) + (uint32_t)j * 16u,
                 B + (size_t)(k0 + r) * ldb + col0 + j * 8);
        }
    };

#pragma unroll
    for (int it = 0; it < S - 1; it++) load_b(it);
    gdc_wait();
#pragma unroll
    for (int it = 0; it < S - 1; it++) {
        load_a(it);
        cp_commit();
    }

    float acc[MF][8][4];
#pragma unroll
    for (int mf = 0; mf < MF; mf++)
#pragma unroll
        for (int nf = 0; nf < 8; nf++)
#pragma unroll
            for (int q = 0; q < 4; q++) acc[mf][nf][q] = 0.0f;

    for (int i = 0; i < niter; i++) {
        cp_wait<S - 2>();
        __syncthreads();
        if (i + S - 1 < niter) {
            load_b(i + S - 1);
            load_a(i + S - 1);
        }
        cp_commit();

        const uint32_t sa = ubase + (uint32_t)((i % S) * STGH) * 2u;
        const uint32_t sb = ubase + (uint32_t)((i % S) * STGH + AH) * 2u;

#pragma unroll
        for (int ks = 0; ks < BK / 16; ks++) {
            uint32_t a[MF][4], b[NC][4];
#pragma unroll
            for (int mf = 0; mf < MF; mf++)
                ldm4(a[mf][0], a[mf][1], a[mf][2], a[mf][3],
                     sa + (a_off + (uint32_t)(mf * 16 * LDRA + ks * 16)) * 2u);
#pragma unroll
            for (int c = 0; c < NC; c++)
                ldm4t(b[c][0], b[c][1], b[c][2], b[c][3],
                      sb + (b_off + (uint32_t)(ks * 16 * LDRB + c * 16)) * 2u);
#pragma unroll
            for (int mf = 0; mf < MF; mf++)
#pragma unroll
                for (int c = 0; c < NC; c++) {
                    mma_f16(acc[mf][2 * c + 0], a[mf], &b[c][0]);
                    mma_f16(acc[mf][2 * c + 1], a[mf], &b[c][2]);
                }
        }
    }

    gdc_launch();

#pragma unroll
    for (int mf = 0; mf < MF; mf++) {
        const int gr0 = row0 + wm * 64 + mf * 16 + gid;
#pragma unroll
        for (int nf = 0; nf < 8; nf++) {
            const int gc = col0 + wn * 64 + nf * 8 + tig * 2;
#pragma unroll
            for (int half_ = 0; half_ < 2; half_++) {
                const int gr = gr0 + half_ * 8;
                float v0 = acc[mf][nf][half_ * 2 + 0];
                float v1 = acc[mf][nf][half_ * 2 + 1];
                float o0, o1;
                if constexpr (EPI == EPI_QKV) {
                    o0 = v0 + e0[gc]; o1 = v1 + e0[gc + 1];
                    if (gc < Dq) { o0 *= QSCALE; o1 *= QSCALE; }
                } else if constexpr (EPI == EPI_GELU) {
                    o0 = gelu_fast(v0 + e0[gc]); o1 = gelu_fast(v1 + e0[gc + 1]);
                } else {  // EPI_RES
                    float2 rr = *(const float2*)&e1[(size_t)gr * ldc + gc];
                    o0 = v0 + e0[gc] + rr.x; o1 = v1 + e0[gc + 1] + rr.y;
                }
                if constexpr (sizeof(CT) == 2) {
                    *(__half2*)&C[(size_t)gr * ldc + gc] = __floats2half2_rn(o0, o1);
                } else {
                    *(float2*)&C[(size_t)gr * ldc + gc] = make_float2(o0, o1);
                }
            }
        }
    }
}

// ---------------------------------------------------------------------------
// launch
// ---------------------------------------------------------------------------
extern "C" void kernel_launch(void* const* d_in, const int* in_sizes, int n_in,
                              void* d_out, int out_size)
{
    const float* x     = (const float*)d_in[0];
    const float* prior = (const float*)d_in[1];
    const float* Wqkv  = (const float*)d_in[2];
    const float* bqkv  = (const float*)d_in[3];
    const float* alpha = (const float*)d_in[4];
    const float* ln1_g = (const float*)d_in[5];
    const float* ln1_b = (const float*)d_in[6];
    const float* ln2_g = (const float*)d_in[7];
    const float* ln2_b = (const float*)d_in[8];
    const float* w1    = (const float*)d_in[9];
    const float* b1    = (const float*)d_in[10];
    const float* w2    = (const float*)d_in[11];
    const float* b2    = (const float*)d_in[12];
    float* out = (float*)d_out;

    __half *zp, *qkvp, *h1p, *whqkv, *wh1, *wh2, *pahp;
    float* s1p;
    cudaGetSymbolAddress((void**)&zp, g_z);
    cudaGetSymbolAddress((void**)&qkvp, g_qkv);
    cudaGetSymbolAddress((void**)&s1p, g_s1);
    cudaGetSymbolAddress((void**)&h1p, g_h1);
    cudaGetSymbolAddress((void**)&whqkv, g_whqkv);
    cudaGetSymbolAddress((void**)&wh1, g_wh1);
    cudaGetSymbolAddress((void**)&wh2, g_wh2);
    cudaGetSymbolAddress((void**)&pahp, g_pah);

    const int smem_g  = 4 * (128 * 72 + 64 * 264) * 2;   // 208896
    const int smem_fa = 5 * 128 * 72 * 2;                // 92160
    cudaFuncSetAttribute(mma_gemm<EPI_QKV, __half>,  cudaFuncAttributeMaxDynamicSharedMemorySize, smem_g);
    cudaFuncSetAttribute(mma_gemm<EPI_GELU, __half>, cudaFuncAttributeMaxDynamicSharedMemorySize, smem_g);
    cudaFuncSetAttribute(mma_gemm<EPI_RES, float>,   cudaFuncAttributeMaxDynamicSharedMemorySize, smem_g);
    cudaFuncSetAttribute(flash_kernel, cudaFuncAttributeMaxDynamicSharedMemorySize, smem_fa);

    const int rows = Bq * Nq;  // 8192

    cudaLaunchAttribute pattr[1];
    pattr[0].id = cudaLaunchAttributeProgrammaticStreamSerialization;
    pattr[0].val.programmaticStreamSerializationAllowed = 1;

    // 0) all casts in one kernel (weights + pre-scaled half prior)
    cast_all_kernel<<<SEG3 / 256, 256>>>(Wqkv, w1, w2, prior, alpha,
                                         whqkv, wh1, wh2, pahp);

    // 1) z = LN1(x)
    {
        cudaLaunchConfig_t cfg{};
        cfg.gridDim = dim3(rows / 8); cfg.blockDim = dim3(256);
        cfg.attrs = pattr; cfg.numAttrs = 1;
        cudaLaunchKernelEx(&cfg, ln_kernel, x, ln1_g, ln1_b, (__half*)zp);
    }
    // 2) qkv = z @ Wqkv + bqkv  (q pre-scaled by F*log2e)
    {
        cudaLaunchConfig_t cfg{};
        cfg.gridDim = dim3(3 * Dq / 256, rows / 128); cfg.blockDim = dim3(256);
        cfg.dynamicSmemBytes = smem_g; cfg.attrs = pattr; cfg.numAttrs = 1;
        cudaLaunchKernelEx(&cfg, mma_gemm<EPI_QKV, __half>,
                           (const __half*)zp, (int)Dq, (const __half*)whqkv, (int)(3 * Dq),
                           (__half*)qkvp, (int)(3 * Dq), (int)Dq, bqkv, (const float*)nullptr);
    }
    // 3) fused attention
    {
        cudaLaunchConfig_t cfg{};
        cfg.gridDim = dim3(Nq / 128, Bq * Hq); cfg.blockDim = dim3(256);
        cfg.dynamicSmemBytes = smem_fa; cfg.attrs = pattr; cfg.numAttrs = 1;
        cudaLaunchKernelEx(&cfg, flash_kernel,
                           (const __half*)qkvp, (const __half*)pahp, x, (float*)s1p);
    }
    // 4) z = LN2(s1)
    {
        cudaLaunchConfig_t cfg{};
        cfg.gridDim = dim3(rows / 8); cfg.blockDim = dim3(256);
        cfg.attrs = pattr; cfg.numAttrs = 1;
        cudaLaunchKernelEx(&cfg, ln_kernel, (const float*)s1p, ln2_g, ln2_b, (__half*)zp);
    }
    // 5) h1 = gelu(z @ w1 + b1)
    {
        cudaLaunchConfig_t cfg{};
        cfg.gridDim = dim3(DFFq / 256, rows / 128); cfg.blockDim = dim3(256);
        cfg.dynamicSmemBytes = smem_g; cfg.attrs = pattr; cfg.numAttrs = 1;
        cudaLaunchKernelEx(&cfg, mma_gemm<EPI_GELU, __half>,
                           (const __half*)zp, (int)Dq, (const __half*)wh1, (int)DFFq,
                           (__half*)h1p, (int)DFFq, (int)Dq, b1, (const float*)nullptr);
    }
    // 6) out = s1 + h1 @ w2 + b2
    {
        cudaLaunchConfig_t cfg{};
        cfg.gridDim = dim3(Dq / 256, rows / 128); cfg.blockDim = dim3(256);
        cfg.dynamicSmemBytes = smem_g; cfg.attrs = pattr; cfg.numAttrs = 1;
        cudaLaunchKernelEx(&cfg, mma_gemm<EPI_RES, float>,
                           (const __half*)h1p, (int)DFFq, (const __half*)wh2, (int)Dq,
                           out, (int)Dq, (int)DFFq, b2, (const float*)s1p);
    }
}